// round 9
// baseline (speedup 1.0000x reference)
#include <cuda_runtime.h>
#include <cstdint>

// SAG_4861902979729: X_out[i] = sum_{e in [rp[i], rp[i+1])} X[ci[e]]
// X [N=100000, D=100] f32. rp [N+1], ci [E] int32/int64 (runtime-detected).
//
// R9: R8's pipelining was DEAD CODE (grid had exactly 1 row per warp). This
// version assigns 4 CONTIGUOUS rows per warp (3125 blocks, 2.6 waves):
//  - one coalesced rp load (lanes 0..4) for all 5 row pointers
//  - one int4 index load per lane covers all 128 neighbor indices
//  - gather body = proven R4 shape (25-lane float4, MLP=4), 1 live acc
// This amortizes the rp->ci dependent startup chain 4x and cuts block-wave
// count ~4x (wave-transition overhead ~11 us -> ~3 us by the T_chip model).

#define D_DIM 100
#define VEC_PER_ROW 25   // 100 floats / 4 per float4
#define ROWS_PER_WARP 4

__device__ __forceinline__ void acc_add(float4& a, const float4& v) {
    a.x += v.x; a.y += v.y; a.z += v.z; a.w += v.w;
}

// Generic single-row path (any degree, any index type).
template <typename IT>
__device__ __forceinline__
void sag_row_generic(const float* __restrict__ X,
                     const IT* __restrict__ rp,
                     const IT* __restrict__ ci,
                     float* __restrict__ out,
                     int row, int lane, bool active, size_t lane_off)
{
    const long long start = (long long)rp[row];
    const int deg = (int)((long long)rp[row + 1] - start);

    float4 acc = make_float4(0.f, 0.f, 0.f, 0.f);
    for (int k0 = 0; k0 < deg; k0 += 32) {
        const int cnt = min(32, deg - k0);
        int my_idx = 0;
        if (lane < cnt) my_idx = (int)__ldcs(ci + start + k0 + lane);
        for (int k = 0; k < cnt; k++) {
            const int j = __shfl_sync(0xffffffffu, my_idx, k);
            if (active) {
                const float4 v = *(const float4*)(X + (size_t)j * D_DIM + lane_off);
                acc_add(acc, v);
            }
        }
    }
    if (active)
        __stcs((float4*)(out + (size_t)row * D_DIM + lane_off), acc);
}

// Fast path: 4 contiguous rows, all degree 32, int32 indices, aligned start.
__device__ __forceinline__
void sag_rows4_fast(const float* __restrict__ X,
                    const int* __restrict__ ci,
                    float* __restrict__ out,
                    int r0, long long s0,
                    int lane, bool active, size_t lane_off)
{
    // One 16B index load per lane: lane l holds indices 4l..4l+3 of the
    // warp's 128 contiguous neighbor indices.
    const int4 idx4 = __ldcs((const int4*)(ci + s0) + lane);

    #pragma unroll
    for (int k = 0; k < ROWS_PER_WARP; k++) {
        float4 acc = make_float4(0.f, 0.f, 0.f, 0.f);
        #pragma unroll
        for (int g = 0; g < 8; g++) {
            const int srcl = 8 * k + g;   // lane holding this group's 4 indices
            const int j0 = __shfl_sync(0xffffffffu, idx4.x, srcl);
            const int j1 = __shfl_sync(0xffffffffu, idx4.y, srcl);
            const int j2 = __shfl_sync(0xffffffffu, idx4.z, srcl);
            const int j3 = __shfl_sync(0xffffffffu, idx4.w, srcl);
            if (active) {
                const float4 v0 = *(const float4*)(X + (size_t)j0 * D_DIM + lane_off);
                const float4 v1 = *(const float4*)(X + (size_t)j1 * D_DIM + lane_off);
                const float4 v2 = *(const float4*)(X + (size_t)j2 * D_DIM + lane_off);
                const float4 v3 = *(const float4*)(X + (size_t)j3 * D_DIM + lane_off);
                acc.x += (v0.x + v1.x) + (v2.x + v3.x);
                acc.y += (v0.y + v1.y) + (v2.y + v3.y);
                acc.z += (v0.z + v1.z) + (v2.z + v3.z);
                acc.w += (v0.w + v1.w) + (v2.w + v3.w);
            }
        }
        if (active)
            __stcs((float4*)(out + (size_t)(r0 + k) * D_DIM + lane_off), acc);
    }
}

__global__ __launch_bounds__(256)
void sag_warp_row_kernel(const float* __restrict__ X,
                         const void* __restrict__ rp_raw,
                         const void* __restrict__ ci_raw,
                         float* __restrict__ out,
                         int n)
{
    const int lane = threadIdx.x & 31;
    const int wg   = (blockIdx.x * blockDim.x + threadIdx.x) >> 5;  // warp id
    const int r0   = wg * ROWS_PER_WARP;
    if (r0 >= n) return;

    const bool active = (lane < VEC_PER_ROW);
    const size_t lane_off = (size_t)lane * 4;

    // Runtime index-width probe: two ALIGNED scalar 4B loads (uniform result).
    // int32 rp: words [0,32,64,...] -> w1 != 0
    // int64 rp: words [0,0,32,0,..] -> w1 == 0 && w2 != 0
    const int* rp_words = (const int*)rp_raw;
    const int w1 = __ldg(rp_words + 1);
    const int w2 = __ldg(rp_words + 2);
    const bool is64 = (w1 == 0) && (w2 != 0);

    if (!is64 && r0 + ROWS_PER_WARP <= n) {
        const int* rp = (const int*)rp_raw;
        const int* ci = (const int*)ci_raw;

        // One coalesced load of rp[r0..r0+4] via lanes 0..4.
        int v = 0;
        if (lane <= ROWS_PER_WARP) v = __ldg(rp + r0 + lane);
        const int p0 = __shfl_sync(0xffffffffu, v, 0);
        const int p1 = __shfl_sync(0xffffffffu, v, 1);
        const int p2 = __shfl_sync(0xffffffffu, v, 2);
        const int p3 = __shfl_sync(0xffffffffu, v, 3);
        const int p4 = __shfl_sync(0xffffffffu, v, 4);

        const bool all32 = (p1 - p0 == 32) && (p2 - p1 == 32) &&
                           (p3 - p2 == 32) && (p4 - p3 == 32) &&
                           ((p0 & 3) == 0);   // int4 alignment of ci + p0
        if (all32) {
            sag_rows4_fast(X, ci, out, r0, (long long)p0,
                           lane, active, lane_off);
            return;
        }
        // Irregular degrees: per-row generic.
        for (int k = 0; k < ROWS_PER_WARP; k++)
            sag_row_generic<int>(X, rp, ci, out, r0 + k,
                                 lane, active, lane_off);
        return;
    }

    // int64 indices, or tail warp with fewer than 4 rows.
    const int rows_here = min(ROWS_PER_WARP, n - r0);
    if (is64) {
        const long long* rp = (const long long*)rp_raw;
        const long long* ci = (const long long*)ci_raw;
        for (int k = 0; k < rows_here; k++)
            sag_row_generic<long long>(X, rp, ci, out, r0 + k,
                                       lane, active, lane_off);
    } else {
        const int* rp = (const int*)rp_raw;
        const int* ci = (const int*)ci_raw;
        for (int k = 0; k < rows_here; k++)
            sag_row_generic<int>(X, rp, ci, out, r0 + k,
                                 lane, active, lane_off);
    }
}

extern "C" void kernel_launch(void* const* d_in, const int* in_sizes, int n_in,
                              void* d_out, int out_size)
{
    const float* X   = (const float*)d_in[0];
    const void*  rp  = d_in[1];
    const void*  ci  = d_in[2];
    float*       out = (float*)d_out;

    const int n = in_sizes[1] - 1;           // row_pointers has N+1 entries

    const int threads = 256;                  // 8 warps/block
    const int rows_per_block = (threads / 32) * ROWS_PER_WARP;  // 32
    const int blocks = (n + rows_per_block - 1) / rows_per_block;

    sag_warp_row_kernel<<<blocks, threads>>>(X, rp, ci, out, n);
}